// round 13
// baseline (speedup 1.0000x reference)
#include <cuda_runtime.h>
#include <math.h>

#define LEN    8192
#define NT     512
#define HN     256
#define BN     8
#define PD(i)  ((i) + ((i) >> 5))   // smem padding: +1 slot per 32

typedef unsigned long long u64;

// K spectra (D and 1/L folded in), float2, coalesced layout [h*LEN + k*512 + t].
__device__ float2 g_khat[(size_t)HN * LEN];   // 16 MB
// Single fwd-convention broadcast twiddle tables, coalesced [k*P + p].
// entry = { wxx=(wx,wx), wyn=(-wy,wy) }; inverse form wyp=(wy,-wy) = lane-swap of wyn.
__device__ ulonglong2 g_T1[4096];   // level1: P=512, m=index      (64 KB)
__device__ ulonglong2 g_T2[256];    // level2: P=32,  m=16*index   (4 KB)
__device__ ulonglong2 g_T3[16];     // level3: P=2,   m=256*index  (256 B)

// ---------- packed f32x2 helpers ----------
__device__ __forceinline__ u64 pk2(float x, float y){
    u64 r; asm("mov.b64 %0, {%1,%2};" : "=l"(r) : "f"(x), "f"(y)); return r;
}
__device__ __forceinline__ float2 upk(u64 v){
    float2 r; asm("mov.b64 {%0,%1}, %2;" : "=f"(r.x), "=f"(r.y) : "l"(v)); return r;
}
__device__ __forceinline__ u64 swp(u64 v){
    u64 r; asm("{\n .reg .f32 a,b;\n mov.b64 {a,b}, %1;\n mov.b64 %0, {b,a};\n}" : "=l"(r) : "l"(v));
    return r;
}
__device__ __forceinline__ u64 f2add(u64 a, u64 b){
    u64 r; asm("add.rn.f32x2 %0, %1, %2;" : "=l"(r) : "l"(a), "l"(b)); return r;
}
__device__ __forceinline__ u64 f2mul(u64 a, u64 b){
    u64 r; asm("mul.rn.f32x2 %0, %1, %2;" : "=l"(r) : "l"(a), "l"(b)); return r;
}
__device__ __forceinline__ u64 f2fma(u64 a, u64 b, u64 c){
    u64 r; asm("fma.rn.f32x2 %0, %1, %2, %3;" : "=l"(r) : "l"(a), "l"(b), "l"(c)); return r;
}
#define NEG1 0xBF800000BF800000ULL

// DIF: a'=a+b; b'=(a-b)*w
__device__ __forceinline__ void bf_fwd(u64& a, u64& b, u64 wxx, u64 wyn){
    u64 sum = f2add(a, b);
    u64 dif = f2fma(b, NEG1, a);
    b = f2fma(swp(dif), wyn, f2mul(dif, wxx));
    a = sum;
}
// DIT inverse: t=b*conj(w); a'=a+t; b'=a-t
__device__ __forceinline__ void bf_inv(u64& a, u64& b, u64 wxx, u64 wyp){
    u64 t = f2fma(swp(b), wyp, f2mul(b, wxx));
    b = f2fma(t, NEG1, a);
    a = f2add(a, t);
}
// square twiddle in place (sign-convention preserving)
__device__ __forceinline__ void csqr_pk(u64& xx, u64& yn){
    u64 t = f2mul(xx, xx);
    u64 s = f2mul(yn, yn);
    u64 m = f2mul(xx, yn);
    xx = f2fma(s, NEG1, t);
    yn = f2add(m, m);
}

__device__ __forceinline__ float fast_tanh(float x){
    float e = __expf(2.0f * x);
    return 1.0f - __fdividef(2.0f, e + 1.0f);
}

// ---------- 4 local stages over 16 register elements (broadcast table base + csqr) ----------
__device__ __forceinline__ void level_fwd_pk(u64 r[16], const ulonglong2* __restrict__ tab,
                                             int p, int P) {
    u64 xx[4], yn[4];
    #pragma unroll
    for (int k = 0; k < 8; ++k) {
        ulonglong2 w = tab[k*P + p];
        if (k < 4) { xx[k] = w.x; yn[k] = w.y; }
        bf_fwd(r[k], r[k+8], w.x, w.y);
    }
    #pragma unroll
    for (int j = 0; j < 4; ++j) {
        csqr_pk(xx[j], yn[j]);
        bf_fwd(r[j],   r[j+4],  xx[j], yn[j]);
        bf_fwd(r[j+8], r[j+12], xx[j], yn[j]);
    }
    #pragma unroll
    for (int j = 0; j < 2; ++j) {
        csqr_pk(xx[j], yn[j]);
        bf_fwd(r[j],    r[j+2],  xx[j], yn[j]);
        bf_fwd(r[j+4],  r[j+6],  xx[j], yn[j]);
        bf_fwd(r[j+8],  r[j+10], xx[j], yn[j]);
        bf_fwd(r[j+12], r[j+14], xx[j], yn[j]);
    }
    csqr_pk(xx[0], yn[0]);
    #pragma unroll
    for (int k = 0; k < 16; k += 2) bf_fwd(r[k], r[k+1], xx[0], yn[0]);
}

// Inverse: loads fwd table; wyp = swp(wyn) (lane swap, no constants, no extra live regs).
__device__ __forceinline__ void level_inv_pk(u64 r[16], const ulonglong2* __restrict__ tab,
                                             int p, int P) {
    u64 xx2[4], yn2[4];
    #pragma unroll
    for (int j = 0; j < 4; ++j) {
        ulonglong2 w = tab[j*P + p];
        xx2[j] = w.x; yn2[j] = swp(w.y);         // (-wy,wy) -> (wy,-wy)
        csqr_pk(xx2[j], yn2[j]);                 // w^2
    }
    u64 xx4a = xx2[0], yn4a = yn2[0]; csqr_pk(xx4a, yn4a);
    u64 xx4b = xx2[1], yn4b = yn2[1]; csqr_pk(xx4b, yn4b);
    u64 xx8 = xx4a, yn8 = yn4a; csqr_pk(xx8, yn8);
    #pragma unroll
    for (int k = 0; k < 16; k += 2) bf_inv(r[k], r[k+1], xx8, yn8);
    bf_inv(r[0],  r[2],  xx4a, yn4a);  bf_inv(r[4],  r[6],  xx4a, yn4a);
    bf_inv(r[8],  r[10], xx4a, yn4a);  bf_inv(r[12], r[14], xx4a, yn4a);
    bf_inv(r[1],  r[3],  xx4b, yn4b);  bf_inv(r[5],  r[7],  xx4b, yn4b);
    bf_inv(r[9],  r[11], xx4b, yn4b);  bf_inv(r[13], r[15], xx4b, yn4b);
    #pragma unroll
    for (int j = 0; j < 4; ++j) {
        bf_inv(r[j],   r[j+4],  xx2[j], yn2[j]);
        bf_inv(r[j+8], r[j+12], xx2[j], yn2[j]);
    }
    #pragma unroll
    for (int k = 0; k < 8; ++k) {
        ulonglong2 w = tab[k*P + p];
        bf_inv(r[k], r[k+8], w.x, swp(w.y));
    }
}

// Final stride-1 stage (w=1): partner is adjacent lane.
__device__ __forceinline__ void shfl_stage_pk(u64 r[16], int t) {
    const float sgn = (t & 1) ? -1.0f : 1.0f;
    #pragma unroll
    for (int k = 0; k < 16; ++k) {
        float2 v = upk(r[k]);
        float ox = __shfl_xor_sync(0xffffffffu, v.x, 1);
        float oy = __shfl_xor_sync(0xffffffffu, v.y, 1);
        r[k] = pk2(fmaf(sgn, v.x, ox), fmaf(sgn, v.y, oy));
    }
}

// Forward FFT: natural order r[k]=x[t+512k] -> scrambled (t,k) layout.
__device__ __forceinline__ void fft_fwd(u64 r[16], u64* sm, int t) {
    level_fwd_pk(r, g_T1, t, 512);
    #pragma unroll
    for (int k = 0; k < 16; ++k) sm[PD(t + 512*k)] = r[k];
    __syncthreads();
    const int base1 = 512*(t >> 5) + (t & 31);
    #pragma unroll
    for (int k = 0; k < 16; ++k) r[k] = sm[PD(base1 + 32*k)];
    level_fwd_pk(r, g_T2, t & 31, 32);
    __syncwarp();
    #pragma unroll
    for (int k = 0; k < 16; ++k) sm[PD(base1 + 32*k)] = r[k];
    __syncwarp();
    const int base2 = 512*(t >> 5) + 32*((t >> 1) & 15) + (t & 1);
    #pragma unroll
    for (int k = 0; k < 16; ++k) r[k] = sm[PD(base2 + 2*k)];
    level_fwd_pk(r, g_T3, t & 1, 2);
    shfl_stage_pk(r, t);
}

// Inverse (unscaled): scrambled -> natural order r[k]=L*x[t+512k].
__device__ __forceinline__ void fft_inv(u64 r[16], u64* sm, int t) {
    shfl_stage_pk(r, t);
    level_inv_pk(r, g_T3, t & 1, 2);
    const int base2 = 512*(t >> 5) + 32*((t >> 1) & 15) + (t & 1);
    const int base1 = 512*(t >> 5) + (t & 31);
    __syncwarp();
    #pragma unroll
    for (int k = 0; k < 16; ++k) sm[PD(base2 + 2*k)] = r[k];
    __syncwarp();
    #pragma unroll
    for (int k = 0; k < 16; ++k) r[k] = sm[PD(base1 + 32*k)];
    level_inv_pk(r, g_T2, t & 31, 32);
    __syncwarp();
    #pragma unroll
    for (int k = 0; k < 16; ++k) sm[PD(base1 + 32*k)] = r[k];
    __syncthreads();
    #pragma unroll
    for (int k = 0; k < 16; ++k) r[k] = sm[PD(t + 512*k)];
    level_inv_pk(r, g_T1, t, 512);
}

// ---------- khat: self-contained twiddles via MUFU sin/cos ----------
#define W8192 (-7.6699039394282067e-4f)   // -2*pi/8192
__device__ __forceinline__ void gen_wb(u64 xx[8], u64 yn[8], int p, int S, int M){
    #pragma unroll
    for (int k = 0; k < 8; ++k) {
        int m = (M * (p + S * k)) & (LEN - 1);
        float s, c; __sincosf(W8192 * (float)m, &s, &c);
        xx[k] = pk2(c, c); yn[k] = pk2(-s, s);
    }
}
__device__ __forceinline__ void level_fwd_gen(u64 r[16], u64 xx[8], u64 yn[8]) {
    #pragma unroll
    for (int k = 0; k < 8; ++k) bf_fwd(r[k], r[k+8], xx[k], yn[k]);
    #pragma unroll
    for (int j = 0; j < 4; ++j) {
        csqr_pk(xx[j], yn[j]);
        bf_fwd(r[j],   r[j+4],  xx[j], yn[j]);
        bf_fwd(r[j+8], r[j+12], xx[j], yn[j]);
    }
    #pragma unroll
    for (int j = 0; j < 2; ++j) {
        csqr_pk(xx[j], yn[j]);
        bf_fwd(r[j],    r[j+2],  xx[j], yn[j]);
        bf_fwd(r[j+4],  r[j+6],  xx[j], yn[j]);
        bf_fwd(r[j+8],  r[j+10], xx[j], yn[j]);
        bf_fwd(r[j+12], r[j+14], xx[j], yn[j]);
    }
    csqr_pk(xx[0], yn[0]);
    #pragma unroll
    for (int k = 0; k < 16; k += 2) bf_fwd(r[k], r[k+1], xx[0], yn[0]);
}
__device__ __forceinline__ void fft_fwd_gen(u64 r[16], u64* sm, int t) {
    u64 xx[8], yn[8];
    gen_wb(xx, yn, t, 512, 1);
    level_fwd_gen(r, xx, yn);
    #pragma unroll
    for (int k = 0; k < 16; ++k) sm[PD(t + 512*k)] = r[k];
    __syncthreads();
    const int base1 = 512*(t >> 5) + (t & 31);
    #pragma unroll
    for (int k = 0; k < 16; ++k) r[k] = sm[PD(base1 + 32*k)];
    gen_wb(xx, yn, t & 31, 32, 16);
    level_fwd_gen(r, xx, yn);
    __syncwarp();
    #pragma unroll
    for (int k = 0; k < 16; ++k) sm[PD(base1 + 32*k)] = r[k];
    __syncwarp();
    const int base2 = 512*(t >> 5) + 32*((t >> 1) & 15) + (t & 1);
    #pragma unroll
    for (int k = 0; k < 16; ++k) r[k] = sm[PD(base2 + 2*k)];
    gen_wb(xx, yn, t & 1, 2, 256);
    level_fwd_gen(r, xx, yn);
    shfl_stage_pk(r, t);
}

// khat: K_hat[h] = (FFT(K[h]) + D[h]) / L, coalesced [k*512+t]; writes shared tables.
__global__ void __launch_bounds__(NT, 2) khat_kernel(const float* __restrict__ K,
                                                     const float* __restrict__ D) {
    extern __shared__ u64 sm[];
    const int h = blockIdx.x;
    const int t = threadIdx.x;

    // Exact-angle table writing (tables consumed 1024x by conv -> keep sincospif).
    const int g = blockIdx.x * NT + t;
    if (g < 4096) {
        float s, c; sincospif(-(float)g / 4096.0f, &s, &c);
        g_T1[g] = make_ulonglong2(pk2(c, c), pk2(-s, s));
        if (g < 256) {
            float s2, c2; sincospif(-(float)(16*g) / 4096.0f, &s2, &c2);
            g_T2[g] = make_ulonglong2(pk2(c2, c2), pk2(-s2, s2));
        }
        if (g < 16) {
            float s3, c3; sincospif(-(float)(256*g) / 4096.0f, &s3, &c3);
            g_T3[g] = make_ulonglong2(pk2(c3, c3), pk2(-s3, s3));
        }
    }

    const float* krow = K + (size_t)h * LEN;
    u64 r[16];
    #pragma unroll
    for (int k = 0; k < 16; ++k) r[k] = pk2(krow[t + 512*k], 0.0f);
    fft_fwd_gen(r, sm, t);
    const float dv = D[h];
    const float invL = 1.0f / (float)LEN;
    float2* out = g_khat + (size_t)h * LEN;
    #pragma unroll
    for (int k = 0; k < 16; ++k) {
        float2 v = upk(r[k]);
        out[k * 512 + t] = make_float2((v.x + dv) * invL, v.y * invL);
    }
}

__global__ void __launch_bounds__(NT, 2) conv_kernel(const float* __restrict__ u,
                                                     float* __restrict__ y) {
    extern __shared__ u64 sm[];
    const int bid = blockIdx.x;           // [0, (BN/2)*HN)
    const int h   = bid >> 2;             // adjacent blocks share khat row -> L2 reuse
    const int bp  = bid & 3;              // batch-pair index
    const int t   = threadIdx.x;

    const size_t row0 = ((size_t)(2*bp) * HN + h) * LEN;
    const size_t row1 = row0 + (size_t)HN * LEN;
    const float* u0 = u + row0;
    const float* u1 = u + row1;

    u64 r[16];
    #pragma unroll
    for (int k = 0; k < 16; ++k)
        r[k] = pk2(__ldcs(u0 + t + 512*k), __ldcs(u1 + t + 512*k));

    fft_fwd(r, sm, t);

    {   // pointwise product with (K_hat + D)/L, coalesced loads
        const float2* kh = g_khat + (size_t)h * LEN;
        #pragma unroll
        for (int k = 0; k < 16; ++k) {
            float2 w = kh[k * 512 + t];
            u64 wxx = pk2(w.x, w.x);
            u64 wyn = pk2(-w.y, w.y);
            r[k] = f2fma(swp(r[k]), wyn, f2mul(r[k], wxx));
        }
    }

    fft_inv(r, sm, t);

    float* y0 = y + row0;
    float* y1 = y + row1;
    #pragma unroll
    for (int k = 0; k < 16; ++k) {
        const int idx = t + 512*k;
        float2 v = upk(r[k]);
        __stcs(y0 + idx, fast_tanh(v.x));
        __stcs(y1 + idx, fast_tanh(v.y));
    }
}

extern "C" void kernel_launch(void* const* d_in, const int* in_sizes, int n_in,
                              void* d_out, int out_size) {
    const float* u = (const float*)d_in[0];   // (B,H,L)
    const float* K = (const float*)d_in[1];   // (H,L)
    const float* D = (const float*)d_in[2];   // (H,)
    float* y = (float*)d_out;                 // (B,H,L)

    const int smem = PD(LEN) * sizeof(u64);   // 67584 B
    cudaFuncSetAttribute(khat_kernel, cudaFuncAttributeMaxDynamicSharedMemorySize, smem);
    cudaFuncSetAttribute(conv_kernel, cudaFuncAttributeMaxDynamicSharedMemorySize, smem);

    khat_kernel<<<HN, NT, smem>>>(K, D);
    conv_kernel<<<(BN/2) * HN, NT, smem>>>(u, y);
}

// round 14
// speedup vs baseline: 1.2574x; 1.2574x over previous
#include <cuda_runtime.h>
#include <math.h>

#define LEN    8192
#define NT     512
#define HN     256
#define BN     8
#define PD(i)  ((i) + ((i) >> 5))   // smem padding: +1 slot per 32

typedef unsigned long long u64;

// K spectra (D and 1/L folded in), float2, coalesced layout [h*LEN + k*512 + t].
__device__ float2 g_khat[(size_t)HN * LEN];   // 16 MB
// Broadcast twiddle tables, coalesced layout [k*P + p].
// entry = { wxx=(wx,wx), wyn=(-wy,wy) } fwd / { wxx, wyp=(wy,-wy) } inv
__device__ ulonglong2 g_T1f[4096], g_T1i[4096];  // level1: P=512, M=1
__device__ ulonglong2 g_T2f[256],  g_T2i[256];   // level2: P=32,  M=16
__device__ ulonglong2 g_T3f[16],   g_T3i[16];    // level3: P=2,   M=256

// ---------- packed f32x2 helpers ----------
__device__ __forceinline__ u64 pk2(float x, float y){
    u64 r; asm("mov.b64 %0, {%1,%2};" : "=l"(r) : "f"(x), "f"(y)); return r;
}
__device__ __forceinline__ float2 upk(u64 v){
    float2 r; asm("mov.b64 {%0,%1}, %2;" : "=f"(r.x), "=f"(r.y) : "l"(v)); return r;
}
__device__ __forceinline__ u64 swp(u64 v){
    u64 r; asm("{\n .reg .f32 a,b;\n mov.b64 {a,b}, %1;\n mov.b64 %0, {b,a};\n}" : "=l"(r) : "l"(v));
    return r;
}
__device__ __forceinline__ u64 f2add(u64 a, u64 b){
    u64 r; asm("add.rn.f32x2 %0, %1, %2;" : "=l"(r) : "l"(a), "l"(b)); return r;
}
__device__ __forceinline__ u64 f2mul(u64 a, u64 b){
    u64 r; asm("mul.rn.f32x2 %0, %1, %2;" : "=l"(r) : "l"(a), "l"(b)); return r;
}
__device__ __forceinline__ u64 f2fma(u64 a, u64 b, u64 c){
    u64 r; asm("fma.rn.f32x2 %0, %1, %2, %3;" : "=l"(r) : "l"(a), "l"(b), "l"(c)); return r;
}
#define NEG1 0xBF800000BF800000ULL

// DIF: a'=a+b; b'=(a-b)*w
__device__ __forceinline__ void bf_fwd(u64& a, u64& b, u64 wxx, u64 wyn){
    u64 sum = f2add(a, b);
    u64 dif = f2fma(b, NEG1, a);
    b = f2fma(swp(dif), wyn, f2mul(dif, wxx));
    a = sum;
}
// DIT inverse: t=b*conj(w); a'=a+t; b'=a-t
__device__ __forceinline__ void bf_inv(u64& a, u64& b, u64 wxx, u64 wyp){
    u64 t = f2fma(swp(b), wyp, f2mul(b, wxx));
    b = f2fma(t, NEG1, a);
    a = f2add(a, t);
}
// square twiddle in place (sign-convention preserving)
__device__ __forceinline__ void csqr_pk(u64& xx, u64& yn){
    u64 t = f2mul(xx, xx);
    u64 s = f2mul(yn, yn);
    u64 m = f2mul(xx, yn);
    xx = f2fma(s, NEG1, t);
    yn = f2add(m, m);
}

__device__ __forceinline__ float fast_tanh(float x){
    float e = __expf(2.0f * x);
    return 1.0f - __fdividef(2.0f, e + 1.0f);
}

// ---------- 4 local stages over 16 register elements (broadcast table base + csqr) ----------
__device__ __forceinline__ void level_fwd_pk(u64 r[16], const ulonglong2* __restrict__ tab,
                                             int p, int P) {
    u64 xx[4], yn[4];
    #pragma unroll
    for (int k = 0; k < 8; ++k) {
        ulonglong2 w = tab[k*P + p];
        if (k < 4) { xx[k] = w.x; yn[k] = w.y; }
        bf_fwd(r[k], r[k+8], w.x, w.y);
    }
    #pragma unroll
    for (int j = 0; j < 4; ++j) {
        csqr_pk(xx[j], yn[j]);
        bf_fwd(r[j],   r[j+4],  xx[j], yn[j]);
        bf_fwd(r[j+8], r[j+12], xx[j], yn[j]);
    }
    #pragma unroll
    for (int j = 0; j < 2; ++j) {
        csqr_pk(xx[j], yn[j]);
        bf_fwd(r[j],    r[j+2],  xx[j], yn[j]);
        bf_fwd(r[j+4],  r[j+6],  xx[j], yn[j]);
        bf_fwd(r[j+8],  r[j+10], xx[j], yn[j]);
        bf_fwd(r[j+12], r[j+14], xx[j], yn[j]);
    }
    csqr_pk(xx[0], yn[0]);
    #pragma unroll
    for (int k = 0; k < 16; k += 2) bf_fwd(r[k], r[k+1], xx[0], yn[0]);
}

__device__ __forceinline__ void level_inv_pk(u64 r[16], const ulonglong2* __restrict__ tab,
                                             int p, int P) {
    u64 xx2[4], yn2[4];
    #pragma unroll
    for (int j = 0; j < 4; ++j) {
        ulonglong2 w = tab[j*P + p];
        xx2[j] = w.x; yn2[j] = w.y;
        csqr_pk(xx2[j], yn2[j]);                 // w^2
    }
    u64 xx4a = xx2[0], yn4a = yn2[0]; csqr_pk(xx4a, yn4a);
    u64 xx4b = xx2[1], yn4b = yn2[1]; csqr_pk(xx4b, yn4b);
    u64 xx8 = xx4a, yn8 = yn4a; csqr_pk(xx8, yn8);
    #pragma unroll
    for (int k = 0; k < 16; k += 2) bf_inv(r[k], r[k+1], xx8, yn8);
    bf_inv(r[0],  r[2],  xx4a, yn4a);  bf_inv(r[4],  r[6],  xx4a, yn4a);
    bf_inv(r[8],  r[10], xx4a, yn4a);  bf_inv(r[12], r[14], xx4a, yn4a);
    bf_inv(r[1],  r[3],  xx4b, yn4b);  bf_inv(r[5],  r[7],  xx4b, yn4b);
    bf_inv(r[9],  r[11], xx4b, yn4b);  bf_inv(r[13], r[15], xx4b, yn4b);
    #pragma unroll
    for (int j = 0; j < 4; ++j) {
        bf_inv(r[j],   r[j+4],  xx2[j], yn2[j]);
        bf_inv(r[j+8], r[j+12], xx2[j], yn2[j]);
    }
    #pragma unroll
    for (int k = 0; k < 8; ++k) {
        ulonglong2 w = tab[k*P + p];
        bf_inv(r[k], r[k+8], w.x, w.y);
    }
}

// Final stride-1 stage (w=1): partner is adjacent lane.
__device__ __forceinline__ void shfl_stage_pk(u64 r[16], int t) {
    const float sgn = (t & 1) ? -1.0f : 1.0f;
    #pragma unroll
    for (int k = 0; k < 16; ++k) {
        float2 v = upk(r[k]);
        float ox = __shfl_xor_sync(0xffffffffu, v.x, 1);
        float oy = __shfl_xor_sync(0xffffffffu, v.y, 1);
        r[k] = pk2(fmaf(sgn, v.x, ox), fmaf(sgn, v.y, oy));
    }
}

// Forward FFT: natural order r[k]=x[t+512k] -> scrambled (t,k) layout.
__device__ __forceinline__ void fft_fwd(u64 r[16], u64* sm, int t) {
    level_fwd_pk(r, g_T1f, t, 512);
    #pragma unroll
    for (int k = 0; k < 16; ++k) sm[PD(t + 512*k)] = r[k];
    __syncthreads();
    const int base1 = 512*(t >> 5) + (t & 31);
    #pragma unroll
    for (int k = 0; k < 16; ++k) r[k] = sm[PD(base1 + 32*k)];
    level_fwd_pk(r, g_T2f, t & 31, 32);
    __syncwarp();
    #pragma unroll
    for (int k = 0; k < 16; ++k) sm[PD(base1 + 32*k)] = r[k];
    __syncwarp();
    const int base2 = 512*(t >> 5) + 32*((t >> 1) & 15) + (t & 1);
    #pragma unroll
    for (int k = 0; k < 16; ++k) r[k] = sm[PD(base2 + 2*k)];
    level_fwd_pk(r, g_T3f, t & 1, 2);
    shfl_stage_pk(r, t);
}

// Inverse (unscaled): scrambled -> natural order r[k]=L*x[t+512k].
__device__ __forceinline__ void fft_inv(u64 r[16], u64* sm, int t) {
    shfl_stage_pk(r, t);
    level_inv_pk(r, g_T3i, t & 1, 2);
    const int base2 = 512*(t >> 5) + 32*((t >> 1) & 15) + (t & 1);
    const int base1 = 512*(t >> 5) + (t & 31);
    __syncwarp();
    #pragma unroll
    for (int k = 0; k < 16; ++k) sm[PD(base2 + 2*k)] = r[k];
    __syncwarp();
    #pragma unroll
    for (int k = 0; k < 16; ++k) r[k] = sm[PD(base1 + 32*k)];
    level_inv_pk(r, g_T2i, t & 31, 32);
    __syncwarp();
    #pragma unroll
    for (int k = 0; k < 16; ++k) sm[PD(base1 + 32*k)] = r[k];
    __syncthreads();
    #pragma unroll
    for (int k = 0; k < 16; ++k) r[k] = sm[PD(t + 512*k)];
    level_inv_pk(r, g_T1i, t, 512);
}

// ---------- khat: self-contained twiddles via MUFU sin/cos ----------
#define W8192 (-7.6699039394282067e-4f)   // -2*pi/8192
__device__ __forceinline__ void gen_wb(u64 xx[8], u64 yn[8], int p, int S, int M){
    #pragma unroll
    for (int k = 0; k < 8; ++k) {
        int m = (M * (p + S * k)) & (LEN - 1);
        float s, c; __sincosf(W8192 * (float)m, &s, &c);
        xx[k] = pk2(c, c); yn[k] = pk2(-s, s);
    }
}
__device__ __forceinline__ void level_fwd_gen(u64 r[16], u64 xx[8], u64 yn[8]) {
    #pragma unroll
    for (int k = 0; k < 8; ++k) bf_fwd(r[k], r[k+8], xx[k], yn[k]);
    #pragma unroll
    for (int j = 0; j < 4; ++j) {
        csqr_pk(xx[j], yn[j]);
        bf_fwd(r[j],   r[j+4],  xx[j], yn[j]);
        bf_fwd(r[j+8], r[j+12], xx[j], yn[j]);
    }
    #pragma unroll
    for (int j = 0; j < 2; ++j) {
        csqr_pk(xx[j], yn[j]);
        bf_fwd(r[j],    r[j+2],  xx[j], yn[j]);
        bf_fwd(r[j+4],  r[j+6],  xx[j], yn[j]);
        bf_fwd(r[j+8],  r[j+10], xx[j], yn[j]);
        bf_fwd(r[j+12], r[j+14], xx[j], yn[j]);
    }
    csqr_pk(xx[0], yn[0]);
    #pragma unroll
    for (int k = 0; k < 16; k += 2) bf_fwd(r[k], r[k+1], xx[0], yn[0]);
}
__device__ __forceinline__ void fft_fwd_gen(u64 r[16], u64* sm, int t) {
    u64 xx[8], yn[8];
    gen_wb(xx, yn, t, 512, 1);
    level_fwd_gen(r, xx, yn);
    #pragma unroll
    for (int k = 0; k < 16; ++k) sm[PD(t + 512*k)] = r[k];
    __syncthreads();
    const int base1 = 512*(t >> 5) + (t & 31);
    #pragma unroll
    for (int k = 0; k < 16; ++k) r[k] = sm[PD(base1 + 32*k)];
    gen_wb(xx, yn, t & 31, 32, 16);
    level_fwd_gen(r, xx, yn);
    __syncwarp();
    #pragma unroll
    for (int k = 0; k < 16; ++k) sm[PD(base1 + 32*k)] = r[k];
    __syncwarp();
    const int base2 = 512*(t >> 5) + 32*((t >> 1) & 15) + (t & 1);
    #pragma unroll
    for (int k = 0; k < 16; ++k) r[k] = sm[PD(base2 + 2*k)];
    gen_wb(xx, yn, t & 1, 2, 256);
    level_fwd_gen(r, xx, yn);
    shfl_stage_pk(r, t);
}

// khat: K_hat[h] = (FFT(K[h]) + D[h]) / L, coalesced [k*512+t]; also writes conv tables.
__global__ void __launch_bounds__(NT, 2) khat_kernel(const float* __restrict__ K,
                                                     const float* __restrict__ D) {
    extern __shared__ u64 sm[];
    const int h = blockIdx.x;
    const int t = threadIdx.x;

    const int g = blockIdx.x * NT + t;
    if (g < 4096) {
        float s, c; sincospif(-(float)g / 4096.0f, &s, &c);
        g_T1f[g] = make_ulonglong2(pk2(c, c), pk2(-s, s));
        g_T1i[g] = make_ulonglong2(pk2(c, c), pk2(s, -s));
        if (g < 256) {
            float s2, c2; sincospif(-(float)(16*g) / 4096.0f, &s2, &c2);
            g_T2f[g] = make_ulonglong2(pk2(c2, c2), pk2(-s2, s2));
            g_T2i[g] = make_ulonglong2(pk2(c2, c2), pk2(s2, -s2));
        }
        if (g < 16) {
            float s3, c3; sincospif(-(float)(256*g) / 4096.0f, &s3, &c3);
            g_T3f[g] = make_ulonglong2(pk2(c3, c3), pk2(-s3, s3));
            g_T3i[g] = make_ulonglong2(pk2(c3, c3), pk2(s3, -s3));
        }
    }

    const float* krow = K + (size_t)h * LEN;
    u64 r[16];
    #pragma unroll
    for (int k = 0; k < 16; ++k) r[k] = pk2(krow[t + 512*k], 0.0f);
    fft_fwd_gen(r, sm, t);
    const float dv = D[h];
    const float invL = 1.0f / (float)LEN;
    float2* out = g_khat + (size_t)h * LEN;
    #pragma unroll
    for (int k = 0; k < 16; ++k) {
        float2 v = upk(r[k]);
        out[k * 512 + t] = make_float2((v.x + dv) * invL, v.y * invL);
    }
}

__global__ void __launch_bounds__(NT, 2) conv_kernel(const float* __restrict__ u,
                                                     float* __restrict__ y) {
    extern __shared__ u64 sm[];
    const int bid = blockIdx.x;           // [0, (BN/2)*HN)
    const int h   = bid >> 2;             // adjacent blocks share khat row -> L2 reuse
    const int bp  = bid & 3;              // batch-pair index
    const int t   = threadIdx.x;

    const size_t row0 = ((size_t)(2*bp) * HN + h) * LEN;
    const size_t row1 = row0 + (size_t)HN * LEN;
    const float* u0 = u + row0;
    const float* u1 = u + row1;

    u64 r[16];
    #pragma unroll
    for (int k = 0; k < 16; ++k)
        r[k] = pk2(__ldcs(u0 + t + 512*k), __ldcs(u1 + t + 512*k));

    fft_fwd(r, sm, t);

    {   // pointwise product with (K_hat + D)/L, coalesced loads
        const float2* kh = g_khat + (size_t)h * LEN;
        #pragma unroll
        for (int k = 0; k < 16; ++k) {
            float2 w = kh[k * 512 + t];
            u64 wxx = pk2(w.x, w.x);
            u64 wyn = pk2(-w.y, w.y);
            r[k] = f2fma(swp(r[k]), wyn, f2mul(r[k], wxx));
        }
    }

    fft_inv(r, sm, t);

    float* y0 = y + row0;
    float* y1 = y + row1;
    #pragma unroll
    for (int k = 0; k < 16; ++k) {
        const int idx = t + 512*k;
        float2 v = upk(r[k]);
        __stcs(y0 + idx, fast_tanh(v.x));
        __stcs(y1 + idx, fast_tanh(v.y));
    }
}

extern "C" void kernel_launch(void* const* d_in, const int* in_sizes, int n_in,
                              void* d_out, int out_size) {
    const float* u = (const float*)d_in[0];   // (B,H,L)
    const float* K = (const float*)d_in[1];   // (H,L)
    const float* D = (const float*)d_in[2];   // (H,)
    float* y = (float*)d_out;                 // (B,H,L)

    const int smem = PD(LEN) * sizeof(u64);   // 67584 B
    cudaFuncSetAttribute(khat_kernel, cudaFuncAttributeMaxDynamicSharedMemorySize, smem);
    cudaFuncSetAttribute(conv_kernel, cudaFuncAttributeMaxDynamicSharedMemorySize, smem);

    khat_kernel<<<HN, NT, smem>>>(K, D);
    conv_kernel<<<(BN/2) * HN, NT, smem>>>(u, y);
}

// round 15
// speedup vs baseline: 1.2845x; 1.0216x over previous
#include <cuda_runtime.h>
#include <math.h>

#define LEN    8192
#define NT     512
#define HN     256
#define BN     8
#define PD(i)  ((i) + ((i) >> 5))   // smem padding: +1 slot per 32

typedef unsigned long long u64;

// K spectra (D and 1/L folded in), float2, coalesced layout [h*LEN + k*512 + t].
__device__ float2 g_khat[(size_t)HN * LEN];   // 16 MB
// Broadcast twiddle tables, coalesced layout [k*P + p].
// entry = { wxx=(wx,wx), wyn=(-wy,wy) } fwd / { wxx, wyp=(wy,-wy) } inv
__device__ ulonglong2 g_T1f[4096], g_T1i[4096];  // level1: P=512, M=1
__device__ ulonglong2 g_T2f[256],  g_T2i[256];   // level2: P=32,  M=16
__device__ ulonglong2 g_T3f[16],   g_T3i[16];    // level3: P=2,   M=256

// ---------- packed f32x2 helpers ----------
__device__ __forceinline__ u64 pk2(float x, float y){
    u64 r; asm("mov.b64 %0, {%1,%2};" : "=l"(r) : "f"(x), "f"(y)); return r;
}
__device__ __forceinline__ float2 upk(u64 v){
    float2 r; asm("mov.b64 {%0,%1}, %2;" : "=f"(r.x), "=f"(r.y) : "l"(v)); return r;
}
__device__ __forceinline__ u64 swp(u64 v){
    u64 r; asm("{\n .reg .f32 a,b;\n mov.b64 {a,b}, %1;\n mov.b64 %0, {b,a};\n}" : "=l"(r) : "l"(v));
    return r;
}
__device__ __forceinline__ u64 f2add(u64 a, u64 b){
    u64 r; asm("add.rn.f32x2 %0, %1, %2;" : "=l"(r) : "l"(a), "l"(b)); return r;
}
__device__ __forceinline__ u64 f2mul(u64 a, u64 b){
    u64 r; asm("mul.rn.f32x2 %0, %1, %2;" : "=l"(r) : "l"(a), "l"(b)); return r;
}
__device__ __forceinline__ u64 f2fma(u64 a, u64 b, u64 c){
    u64 r; asm("fma.rn.f32x2 %0, %1, %2, %3;" : "=l"(r) : "l"(a), "l"(b), "l"(c)); return r;
}
#define NEG1 0xBF800000BF800000ULL

// Hardware tanh (MUFU, sm_75+): 1 instruction replaces 2-MUFU + 3-FMA chain.
__device__ __forceinline__ float tanh_hw(float x){
    float r; asm("tanh.approx.f32 %0, %1;" : "=f"(r) : "f"(x)); return r;
}

// DIF: a'=a+b; b'=(a-b)*w
__device__ __forceinline__ void bf_fwd(u64& a, u64& b, u64 wxx, u64 wyn){
    u64 sum = f2add(a, b);
    u64 dif = f2fma(b, NEG1, a);
    b = f2fma(swp(dif), wyn, f2mul(dif, wxx));
    a = sum;
}
// DIT inverse: t=b*conj(w); a'=a+t; b'=a-t
__device__ __forceinline__ void bf_inv(u64& a, u64& b, u64 wxx, u64 wyp){
    u64 t = f2fma(swp(b), wyp, f2mul(b, wxx));
    b = f2fma(t, NEG1, a);
    a = f2add(a, t);
}
// square twiddle in place (sign-convention preserving)
__device__ __forceinline__ void csqr_pk(u64& xx, u64& yn){
    u64 t = f2mul(xx, xx);
    u64 s = f2mul(yn, yn);
    u64 m = f2mul(xx, yn);
    xx = f2fma(s, NEG1, t);
    yn = f2add(m, m);
}

// ---------- 4 local stages over 16 register elements (broadcast table base + csqr) ----------
__device__ __forceinline__ void level_fwd_pk(u64 r[16], const ulonglong2* __restrict__ tab,
                                             int p, int P) {
    u64 xx[4], yn[4];
    #pragma unroll
    for (int k = 0; k < 8; ++k) {
        ulonglong2 w = tab[k*P + p];
        if (k < 4) { xx[k] = w.x; yn[k] = w.y; }
        bf_fwd(r[k], r[k+8], w.x, w.y);
    }
    #pragma unroll
    for (int j = 0; j < 4; ++j) {
        csqr_pk(xx[j], yn[j]);
        bf_fwd(r[j],   r[j+4],  xx[j], yn[j]);
        bf_fwd(r[j+8], r[j+12], xx[j], yn[j]);
    }
    #pragma unroll
    for (int j = 0; j < 2; ++j) {
        csqr_pk(xx[j], yn[j]);
        bf_fwd(r[j],    r[j+2],  xx[j], yn[j]);
        bf_fwd(r[j+4],  r[j+6],  xx[j], yn[j]);
        bf_fwd(r[j+8],  r[j+10], xx[j], yn[j]);
        bf_fwd(r[j+12], r[j+14], xx[j], yn[j]);
    }
    csqr_pk(xx[0], yn[0]);
    #pragma unroll
    for (int k = 0; k < 16; k += 2) bf_fwd(r[k], r[k+1], xx[0], yn[0]);
}

__device__ __forceinline__ void level_inv_pk(u64 r[16], const ulonglong2* __restrict__ tab,
                                             int p, int P) {
    u64 xx2[4], yn2[4];
    #pragma unroll
    for (int j = 0; j < 4; ++j) {
        ulonglong2 w = tab[j*P + p];
        xx2[j] = w.x; yn2[j] = w.y;
        csqr_pk(xx2[j], yn2[j]);                 // w^2
    }
    u64 xx4a = xx2[0], yn4a = yn2[0]; csqr_pk(xx4a, yn4a);
    u64 xx4b = xx2[1], yn4b = yn2[1]; csqr_pk(xx4b, yn4b);
    u64 xx8 = xx4a, yn8 = yn4a; csqr_pk(xx8, yn8);
    #pragma unroll
    for (int k = 0; k < 16; k += 2) bf_inv(r[k], r[k+1], xx8, yn8);
    bf_inv(r[0],  r[2],  xx4a, yn4a);  bf_inv(r[4],  r[6],  xx4a, yn4a);
    bf_inv(r[8],  r[10], xx4a, yn4a);  bf_inv(r[12], r[14], xx4a, yn4a);
    bf_inv(r[1],  r[3],  xx4b, yn4b);  bf_inv(r[5],  r[7],  xx4b, yn4b);
    bf_inv(r[9],  r[11], xx4b, yn4b);  bf_inv(r[13], r[15], xx4b, yn4b);
    #pragma unroll
    for (int j = 0; j < 4; ++j) {
        bf_inv(r[j],   r[j+4],  xx2[j], yn2[j]);
        bf_inv(r[j+8], r[j+12], xx2[j], yn2[j]);
    }
    #pragma unroll
    for (int k = 0; k < 8; ++k) {
        ulonglong2 w = tab[k*P + p];
        bf_inv(r[k], r[k+8], w.x, w.y);
    }
}

// Final stride-1 stage (w=1): partner is adjacent lane.
__device__ __forceinline__ void shfl_stage_pk(u64 r[16], int t) {
    const float sgn = (t & 1) ? -1.0f : 1.0f;
    #pragma unroll
    for (int k = 0; k < 16; ++k) {
        float2 v = upk(r[k]);
        float ox = __shfl_xor_sync(0xffffffffu, v.x, 1);
        float oy = __shfl_xor_sync(0xffffffffu, v.y, 1);
        r[k] = pk2(fmaf(sgn, v.x, ox), fmaf(sgn, v.y, oy));
    }
}

// Forward FFT: natural order r[k]=x[t+512k] -> scrambled (t,k) layout.
__device__ __forceinline__ void fft_fwd(u64 r[16], u64* sm, int t) {
    level_fwd_pk(r, g_T1f, t, 512);
    #pragma unroll
    for (int k = 0; k < 16; ++k) sm[PD(t + 512*k)] = r[k];
    __syncthreads();
    const int base1 = 512*(t >> 5) + (t & 31);
    #pragma unroll
    for (int k = 0; k < 16; ++k) r[k] = sm[PD(base1 + 32*k)];
    level_fwd_pk(r, g_T2f, t & 31, 32);
    __syncwarp();
    #pragma unroll
    for (int k = 0; k < 16; ++k) sm[PD(base1 + 32*k)] = r[k];
    __syncwarp();
    const int base2 = 512*(t >> 5) + 32*((t >> 1) & 15) + (t & 1);
    #pragma unroll
    for (int k = 0; k < 16; ++k) r[k] = sm[PD(base2 + 2*k)];
    level_fwd_pk(r, g_T3f, t & 1, 2);
    shfl_stage_pk(r, t);
}

// Inverse (unscaled): scrambled -> natural order r[k]=L*x[t+512k].
__device__ __forceinline__ void fft_inv(u64 r[16], u64* sm, int t) {
    shfl_stage_pk(r, t);
    level_inv_pk(r, g_T3i, t & 1, 2);
    const int base2 = 512*(t >> 5) + 32*((t >> 1) & 15) + (t & 1);
    const int base1 = 512*(t >> 5) + (t & 31);
    __syncwarp();
    #pragma unroll
    for (int k = 0; k < 16; ++k) sm[PD(base2 + 2*k)] = r[k];
    __syncwarp();
    #pragma unroll
    for (int k = 0; k < 16; ++k) r[k] = sm[PD(base1 + 32*k)];
    level_inv_pk(r, g_T2i, t & 31, 32);
    __syncwarp();
    #pragma unroll
    for (int k = 0; k < 16; ++k) sm[PD(base1 + 32*k)] = r[k];
    __syncthreads();
    #pragma unroll
    for (int k = 0; k < 16; ++k) r[k] = sm[PD(t + 512*k)];
    level_inv_pk(r, g_T1i, t, 512);
}

// ---------- khat: self-contained twiddles via MUFU sin/cos ----------
#define W8192 (-7.6699039394282067e-4f)   // -2*pi/8192
__device__ __forceinline__ void gen_wb(u64 xx[8], u64 yn[8], int p, int S, int M){
    #pragma unroll
    for (int k = 0; k < 8; ++k) {
        int m = (M * (p + S * k)) & (LEN - 1);
        float s, c; __sincosf(W8192 * (float)m, &s, &c);
        xx[k] = pk2(c, c); yn[k] = pk2(-s, s);
    }
}
__device__ __forceinline__ void level_fwd_gen(u64 r[16], u64 xx[8], u64 yn[8]) {
    #pragma unroll
    for (int k = 0; k < 8; ++k) bf_fwd(r[k], r[k+8], xx[k], yn[k]);
    #pragma unroll
    for (int j = 0; j < 4; ++j) {
        csqr_pk(xx[j], yn[j]);
        bf_fwd(r[j],   r[j+4],  xx[j], yn[j]);
        bf_fwd(r[j+8], r[j+12], xx[j], yn[j]);
    }
    #pragma unroll
    for (int j = 0; j < 2; ++j) {
        csqr_pk(xx[j], yn[j]);
        bf_fwd(r[j],    r[j+2],  xx[j], yn[j]);
        bf_fwd(r[j+4],  r[j+6],  xx[j], yn[j]);
        bf_fwd(r[j+8],  r[j+10], xx[j], yn[j]);
        bf_fwd(r[j+12], r[j+14], xx[j], yn[j]);
    }
    csqr_pk(xx[0], yn[0]);
    #pragma unroll
    for (int k = 0; k < 16; k += 2) bf_fwd(r[k], r[k+1], xx[0], yn[0]);
}
__device__ __forceinline__ void fft_fwd_gen(u64 r[16], u64* sm, int t) {
    u64 xx[8], yn[8];
    gen_wb(xx, yn, t, 512, 1);
    level_fwd_gen(r, xx, yn);
    #pragma unroll
    for (int k = 0; k < 16; ++k) sm[PD(t + 512*k)] = r[k];
    __syncthreads();
    const int base1 = 512*(t >> 5) + (t & 31);
    #pragma unroll
    for (int k = 0; k < 16; ++k) r[k] = sm[PD(base1 + 32*k)];
    gen_wb(xx, yn, t & 31, 32, 16);
    level_fwd_gen(r, xx, yn);
    __syncwarp();
    #pragma unroll
    for (int k = 0; k < 16; ++k) sm[PD(base1 + 32*k)] = r[k];
    __syncwarp();
    const int base2 = 512*(t >> 5) + 32*((t >> 1) & 15) + (t & 1);
    #pragma unroll
    for (int k = 0; k < 16; ++k) r[k] = sm[PD(base2 + 2*k)];
    gen_wb(xx, yn, t & 1, 2, 256);
    level_fwd_gen(r, xx, yn);
    shfl_stage_pk(r, t);
}

// khat: K_hat[h] = (FFT(K[h]) + D[h]) / L, coalesced [k*512+t]; also writes conv tables.
__global__ void __launch_bounds__(NT, 2) khat_kernel(const float* __restrict__ K,
                                                     const float* __restrict__ D) {
    extern __shared__ u64 sm[];
    const int h = blockIdx.x;
    const int t = threadIdx.x;

    const int g = blockIdx.x * NT + t;
    if (g < 4096) {
        float s, c; sincospif(-(float)g / 4096.0f, &s, &c);
        g_T1f[g] = make_ulonglong2(pk2(c, c), pk2(-s, s));
        g_T1i[g] = make_ulonglong2(pk2(c, c), pk2(s, -s));
        if (g < 256) {
            float s2, c2; sincospif(-(float)(16*g) / 4096.0f, &s2, &c2);
            g_T2f[g] = make_ulonglong2(pk2(c2, c2), pk2(-s2, s2));
            g_T2i[g] = make_ulonglong2(pk2(c2, c2), pk2(s2, -s2));
        }
        if (g < 16) {
            float s3, c3; sincospif(-(float)(256*g) / 4096.0f, &s3, &c3);
            g_T3f[g] = make_ulonglong2(pk2(c3, c3), pk2(-s3, s3));
            g_T3i[g] = make_ulonglong2(pk2(c3, c3), pk2(s3, -s3));
        }
    }

    const float* krow = K + (size_t)h * LEN;
    u64 r[16];
    #pragma unroll
    for (int k = 0; k < 16; ++k) r[k] = pk2(krow[t + 512*k], 0.0f);
    fft_fwd_gen(r, sm, t);
    const float dv = D[h];
    const float invL = 1.0f / (float)LEN;
    float2* out = g_khat + (size_t)h * LEN;
    #pragma unroll
    for (int k = 0; k < 16; ++k) {
        float2 v = upk(r[k]);
        out[k * 512 + t] = make_float2((v.x + dv) * invL, v.y * invL);
    }
}

__global__ void __launch_bounds__(NT, 2) conv_kernel(const float* __restrict__ u,
                                                     float* __restrict__ y) {
    extern __shared__ u64 sm[];
    const int bid = blockIdx.x;           // [0, (BN/2)*HN)
    const int h   = bid >> 2;             // adjacent blocks share khat row -> L2 reuse
    const int bp  = bid & 3;              // batch-pair index
    const int t   = threadIdx.x;

    const size_t row0 = ((size_t)(2*bp) * HN + h) * LEN;
    const size_t row1 = row0 + (size_t)HN * LEN;
    const float* u0 = u + row0;
    const float* u1 = u + row1;

    u64 r[16];
    #pragma unroll
    for (int k = 0; k < 16; ++k)
        r[k] = pk2(__ldcs(u0 + t + 512*k), __ldcs(u1 + t + 512*k));

    fft_fwd(r, sm, t);

    {   // pointwise product with (K_hat + D)/L, coalesced loads
        const float2* kh = g_khat + (size_t)h * LEN;
        #pragma unroll
        for (int k = 0; k < 16; ++k) {
            float2 w = kh[k * 512 + t];
            u64 wxx = pk2(w.x, w.x);
            u64 wyn = pk2(-w.y, w.y);
            r[k] = f2fma(swp(r[k]), wyn, f2mul(r[k], wxx));
        }
    }

    fft_inv(r, sm, t);

    float* y0 = y + row0;
    float* y1 = y + row1;
    #pragma unroll
    for (int k = 0; k < 16; ++k) {
        const int idx = t + 512*k;
        float2 v = upk(r[k]);
        __stcs(y0 + idx, tanh_hw(v.x));
        __stcs(y1 + idx, tanh_hw(v.y));
    }
}

extern "C" void kernel_launch(void* const* d_in, const int* in_sizes, int n_in,
                              void* d_out, int out_size) {
    const float* u = (const float*)d_in[0];   // (B,H,L)
    const float* K = (const float*)d_in[1];   // (H,L)
    const float* D = (const float*)d_in[2];   // (H,)
    float* y = (float*)d_out;                 // (B,H,L)

    const int smem = PD(LEN) * sizeof(u64);   // 67584 B
    cudaFuncSetAttribute(khat_kernel, cudaFuncAttributeMaxDynamicSharedMemorySize, smem);
    cudaFuncSetAttribute(conv_kernel, cudaFuncAttributeMaxDynamicSharedMemorySize, smem);

    khat_kernel<<<HN, NT, smem>>>(K, D);
    conv_kernel<<<(BN/2) * HN, NT, smem>>>(u, y);
}

// round 16
// speedup vs baseline: 1.2850x; 1.0004x over previous
#include <cuda_runtime.h>
#include <math.h>

#define LEN    8192
#define NT     512
#define HN     256
#define BN     8
#define PD(i)  ((i) + ((i) >> 5))   // smem padding: +1 slot per 32

typedef unsigned long long u64;

// K spectra (D and 1/L folded in), float2, coalesced layout [h*LEN + k*512 + t].
__device__ float2 g_khat[(size_t)HN * LEN];   // 16 MB
// Broadcast twiddle tables, coalesced layout [k*P + p].
// entry = { wxx=(wx,wx), wyn=(-wy,wy) } fwd / { wxx, wyp=(wy,-wy) } inv
__device__ ulonglong2 g_T1f[4096], g_T1i[4096];  // level1: P=512, M=1
__device__ ulonglong2 g_T2f[256],  g_T2i[256];   // level2: P=32,  M=16
// Level-3 FULL rows (15 twiddles: 8 base, 4 sq, 2 quad, 1 oct) for p in {0,1}.
// Only 2 rows -> all lanes broadcast-load; replaces the serial csqr chains.
__device__ ulonglong2 g_C3f[2*15], g_C3i[2*15];

// ---------- packed f32x2 helpers ----------
__device__ __forceinline__ u64 pk2(float x, float y){
    u64 r; asm("mov.b64 %0, {%1,%2};" : "=l"(r) : "f"(x), "f"(y)); return r;
}
__device__ __forceinline__ float2 upk(u64 v){
    float2 r; asm("mov.b64 {%0,%1}, %2;" : "=f"(r.x), "=f"(r.y) : "l"(v)); return r;
}
__device__ __forceinline__ u64 swp(u64 v){
    u64 r; asm("{\n .reg .f32 a,b;\n mov.b64 {a,b}, %1;\n mov.b64 %0, {b,a};\n}" : "=l"(r) : "l"(v));
    return r;
}
__device__ __forceinline__ u64 f2add(u64 a, u64 b){
    u64 r; asm("add.rn.f32x2 %0, %1, %2;" : "=l"(r) : "l"(a), "l"(b)); return r;
}
__device__ __forceinline__ u64 f2mul(u64 a, u64 b){
    u64 r; asm("mul.rn.f32x2 %0, %1, %2;" : "=l"(r) : "l"(a), "l"(b)); return r;
}
__device__ __forceinline__ u64 f2fma(u64 a, u64 b, u64 c){
    u64 r; asm("fma.rn.f32x2 %0, %1, %2, %3;" : "=l"(r) : "l"(a), "l"(b), "l"(c)); return r;
}
#define NEG1 0xBF800000BF800000ULL

// Hardware tanh (MUFU, sm_75+).
__device__ __forceinline__ float tanh_hw(float x){
    float r; asm("tanh.approx.f32 %0, %1;" : "=f"(r) : "f"(x)); return r;
}

// DIF: a'=a+b; b'=(a-b)*w
__device__ __forceinline__ void bf_fwd(u64& a, u64& b, u64 wxx, u64 wyn){
    u64 sum = f2add(a, b);
    u64 dif = f2fma(b, NEG1, a);
    b = f2fma(swp(dif), wyn, f2mul(dif, wxx));
    a = sum;
}
// DIT inverse: t=b*conj(w); a'=a+t; b'=a-t
__device__ __forceinline__ void bf_inv(u64& a, u64& b, u64 wxx, u64 wyp){
    u64 t = f2fma(swp(b), wyp, f2mul(b, wxx));
    b = f2fma(t, NEG1, a);
    a = f2add(a, t);
}
// square twiddle in place (sign-convention preserving)
__device__ __forceinline__ void csqr_pk(u64& xx, u64& yn){
    u64 t = f2mul(xx, xx);
    u64 s = f2mul(yn, yn);
    u64 m = f2mul(xx, yn);
    xx = f2fma(s, NEG1, t);
    yn = f2add(m, m);
}

// ---------- levels 1/2: lazy table loads + csqr (R6-proven) ----------
__device__ __forceinline__ void level_fwd_pk(u64 r[16], const ulonglong2* __restrict__ tab,
                                             int p, int P) {
    u64 xx[4], yn[4];
    #pragma unroll
    for (int k = 0; k < 8; ++k) {
        ulonglong2 w = tab[k*P + p];
        if (k < 4) { xx[k] = w.x; yn[k] = w.y; }
        bf_fwd(r[k], r[k+8], w.x, w.y);
    }
    #pragma unroll
    for (int j = 0; j < 4; ++j) {
        csqr_pk(xx[j], yn[j]);
        bf_fwd(r[j],   r[j+4],  xx[j], yn[j]);
        bf_fwd(r[j+8], r[j+12], xx[j], yn[j]);
    }
    #pragma unroll
    for (int j = 0; j < 2; ++j) {
        csqr_pk(xx[j], yn[j]);
        bf_fwd(r[j],    r[j+2],  xx[j], yn[j]);
        bf_fwd(r[j+4],  r[j+6],  xx[j], yn[j]);
        bf_fwd(r[j+8],  r[j+10], xx[j], yn[j]);
        bf_fwd(r[j+12], r[j+14], xx[j], yn[j]);
    }
    csqr_pk(xx[0], yn[0]);
    #pragma unroll
    for (int k = 0; k < 16; k += 2) bf_fwd(r[k], r[k+1], xx[0], yn[0]);
}

__device__ __forceinline__ void level_inv_pk(u64 r[16], const ulonglong2* __restrict__ tab,
                                             int p, int P) {
    u64 xx2[4], yn2[4];
    #pragma unroll
    for (int j = 0; j < 4; ++j) {
        ulonglong2 w = tab[j*P + p];
        xx2[j] = w.x; yn2[j] = w.y;
        csqr_pk(xx2[j], yn2[j]);                 // w^2
    }
    u64 xx4a = xx2[0], yn4a = yn2[0]; csqr_pk(xx4a, yn4a);
    u64 xx4b = xx2[1], yn4b = yn2[1]; csqr_pk(xx4b, yn4b);
    u64 xx8 = xx4a, yn8 = yn4a; csqr_pk(xx8, yn8);
    #pragma unroll
    for (int k = 0; k < 16; k += 2) bf_inv(r[k], r[k+1], xx8, yn8);
    bf_inv(r[0],  r[2],  xx4a, yn4a);  bf_inv(r[4],  r[6],  xx4a, yn4a);
    bf_inv(r[8],  r[10], xx4a, yn4a);  bf_inv(r[12], r[14], xx4a, yn4a);
    bf_inv(r[1],  r[3],  xx4b, yn4b);  bf_inv(r[5],  r[7],  xx4b, yn4b);
    bf_inv(r[9],  r[11], xx4b, yn4b);  bf_inv(r[13], r[15], xx4b, yn4b);
    #pragma unroll
    for (int j = 0; j < 4; ++j) {
        bf_inv(r[j],   r[j+4],  xx2[j], yn2[j]);
        bf_inv(r[j+8], r[j+12], xx2[j], yn2[j]);
    }
    #pragma unroll
    for (int k = 0; k < 8; ++k) {
        ulonglong2 w = tab[k*P + p];
        bf_inv(r[k], r[k+8], w.x, w.y);
    }
}

// ---------- level 3: full-row broadcast tables (2 rows, load->use->die) ----------
__device__ __forceinline__ void level_fwd_tab3(u64 r[16], const ulonglong2* __restrict__ row) {
    #pragma unroll
    for (int k = 0; k < 8; ++k) { ulonglong2 w = row[k]; bf_fwd(r[k], r[k+8], w.x, w.y); }
    #pragma unroll
    for (int j = 0; j < 4; ++j) {
        ulonglong2 w = row[8+j];
        bf_fwd(r[j],   r[j+4],  w.x, w.y);
        bf_fwd(r[j+8], r[j+12], w.x, w.y);
    }
    #pragma unroll
    for (int j = 0; j < 2; ++j) {
        ulonglong2 w = row[12+j];
        bf_fwd(r[j],    r[j+2],  w.x, w.y);
        bf_fwd(r[j+4],  r[j+6],  w.x, w.y);
        bf_fwd(r[j+8],  r[j+10], w.x, w.y);
        bf_fwd(r[j+12], r[j+14], w.x, w.y);
    }
    { ulonglong2 w = row[14];
      #pragma unroll
      for (int k = 0; k < 16; k += 2) bf_fwd(r[k], r[k+1], w.x, w.y); }
}

__device__ __forceinline__ void level_inv_tab3(u64 r[16], const ulonglong2* __restrict__ row) {
    { ulonglong2 w = row[14];
      #pragma unroll
      for (int k = 0; k < 16; k += 2) bf_inv(r[k], r[k+1], w.x, w.y); }
    #pragma unroll
    for (int j = 0; j < 2; ++j) {
        ulonglong2 w = row[12+j];
        bf_inv(r[j],    r[j+2],  w.x, w.y);
        bf_inv(r[j+4],  r[j+6],  w.x, w.y);
        bf_inv(r[j+8],  r[j+10], w.x, w.y);
        bf_inv(r[j+12], r[j+14], w.x, w.y);
    }
    #pragma unroll
    for (int j = 0; j < 4; ++j) {
        ulonglong2 w = row[8+j];
        bf_inv(r[j],   r[j+4],  w.x, w.y);
        bf_inv(r[j+8], r[j+12], w.x, w.y);
    }
    #pragma unroll
    for (int k = 0; k < 8; ++k) { ulonglong2 w = row[k]; bf_inv(r[k], r[k+8], w.x, w.y); }
}

// Final stride-1 stage (w=1): partner is adjacent lane.
__device__ __forceinline__ void shfl_stage_pk(u64 r[16], int t) {
    const float sgn = (t & 1) ? -1.0f : 1.0f;
    #pragma unroll
    for (int k = 0; k < 16; ++k) {
        float2 v = upk(r[k]);
        float ox = __shfl_xor_sync(0xffffffffu, v.x, 1);
        float oy = __shfl_xor_sync(0xffffffffu, v.y, 1);
        r[k] = pk2(fmaf(sgn, v.x, ox), fmaf(sgn, v.y, oy));
    }
}

// Forward FFT: natural order r[k]=x[t+512k] -> scrambled (t,k) layout.
__device__ __forceinline__ void fft_fwd(u64 r[16], u64* sm, int t) {
    level_fwd_pk(r, g_T1f, t, 512);
    #pragma unroll
    for (int k = 0; k < 16; ++k) sm[PD(t + 512*k)] = r[k];
    __syncthreads();
    const int base1 = 512*(t >> 5) + (t & 31);
    #pragma unroll
    for (int k = 0; k < 16; ++k) r[k] = sm[PD(base1 + 32*k)];
    level_fwd_pk(r, g_T2f, t & 31, 32);
    __syncwarp();
    #pragma unroll
    for (int k = 0; k < 16; ++k) sm[PD(base1 + 32*k)] = r[k];
    __syncwarp();
    const int base2 = 512*(t >> 5) + 32*((t >> 1) & 15) + (t & 1);
    #pragma unroll
    for (int k = 0; k < 16; ++k) r[k] = sm[PD(base2 + 2*k)];
    level_fwd_tab3(r, g_C3f + (t & 1) * 15);
    shfl_stage_pk(r, t);
}

// Inverse (unscaled): scrambled -> natural order r[k]=L*x[t+512k].
__device__ __forceinline__ void fft_inv(u64 r[16], u64* sm, int t) {
    shfl_stage_pk(r, t);
    level_inv_tab3(r, g_C3i + (t & 1) * 15);
    const int base2 = 512*(t >> 5) + 32*((t >> 1) & 15) + (t & 1);
    const int base1 = 512*(t >> 5) + (t & 31);
    __syncwarp();
    #pragma unroll
    for (int k = 0; k < 16; ++k) sm[PD(base2 + 2*k)] = r[k];
    __syncwarp();
    #pragma unroll
    for (int k = 0; k < 16; ++k) r[k] = sm[PD(base1 + 32*k)];
    level_inv_pk(r, g_T2i, t & 31, 32);
    __syncwarp();
    #pragma unroll
    for (int k = 0; k < 16; ++k) sm[PD(base1 + 32*k)] = r[k];
    __syncthreads();
    #pragma unroll
    for (int k = 0; k < 16; ++k) r[k] = sm[PD(t + 512*k)];
    level_inv_pk(r, g_T1i, t, 512);
}

// ---------- khat: self-contained twiddles via MUFU sin/cos ----------
#define W8192 (-7.6699039394282067e-4f)   // -2*pi/8192
__device__ __forceinline__ void gen_wb(u64 xx[8], u64 yn[8], int p, int S, int M){
    #pragma unroll
    for (int k = 0; k < 8; ++k) {
        int m = (M * (p + S * k)) & (LEN - 1);
        float s, c; __sincosf(W8192 * (float)m, &s, &c);
        xx[k] = pk2(c, c); yn[k] = pk2(-s, s);
    }
}
__device__ __forceinline__ void level_fwd_gen(u64 r[16], u64 xx[8], u64 yn[8]) {
    #pragma unroll
    for (int k = 0; k < 8; ++k) bf_fwd(r[k], r[k+8], xx[k], yn[k]);
    #pragma unroll
    for (int j = 0; j < 4; ++j) {
        csqr_pk(xx[j], yn[j]);
        bf_fwd(r[j],   r[j+4],  xx[j], yn[j]);
        bf_fwd(r[j+8], r[j+12], xx[j], yn[j]);
    }
    #pragma unroll
    for (int j = 0; j < 2; ++j) {
        csqr_pk(xx[j], yn[j]);
        bf_fwd(r[j],    r[j+2],  xx[j], yn[j]);
        bf_fwd(r[j+4],  r[j+6],  xx[j], yn[j]);
        bf_fwd(r[j+8],  r[j+10], xx[j], yn[j]);
        bf_fwd(r[j+12], r[j+14], xx[j], yn[j]);
    }
    csqr_pk(xx[0], yn[0]);
    #pragma unroll
    for (int k = 0; k < 16; k += 2) bf_fwd(r[k], r[k+1], xx[0], yn[0]);
}
__device__ __forceinline__ void fft_fwd_gen(u64 r[16], u64* sm, int t) {
    u64 xx[8], yn[8];
    gen_wb(xx, yn, t, 512, 1);
    level_fwd_gen(r, xx, yn);
    #pragma unroll
    for (int k = 0; k < 16; ++k) sm[PD(t + 512*k)] = r[k];
    __syncthreads();
    const int base1 = 512*(t >> 5) + (t & 31);
    #pragma unroll
    for (int k = 0; k < 16; ++k) r[k] = sm[PD(base1 + 32*k)];
    gen_wb(xx, yn, t & 31, 32, 16);
    level_fwd_gen(r, xx, yn);
    __syncwarp();
    #pragma unroll
    for (int k = 0; k < 16; ++k) sm[PD(base1 + 32*k)] = r[k];
    __syncwarp();
    const int base2 = 512*(t >> 5) + 32*((t >> 1) & 15) + (t & 1);
    #pragma unroll
    for (int k = 0; k < 16; ++k) r[k] = sm[PD(base2 + 2*k)];
    gen_wb(xx, yn, t & 1, 2, 256);
    level_fwd_gen(r, xx, yn);
    shfl_stage_pk(r, t);
}

// Write one level-3 full row (p in {0,1}): 8 base (m=256(p+2k)), 4 sq, 2 quad, 1 oct.
__device__ __forceinline__ void write_c3_row(int p, ulonglong2* f, ulonglong2* iv) {
    int idx = 0;
    #pragma unroll
    for (int k = 0; k < 8; ++k, ++idx) {
        int m = (256 * (p + 2*k)) & (LEN - 1);
        float s, c; sincospif(-(float)m / 4096.0f, &s, &c);
        f[idx]  = make_ulonglong2(pk2(c, c), pk2(-s, s));
        iv[idx] = make_ulonglong2(pk2(c, c), pk2(s, -s));
    }
    #pragma unroll
    for (int j = 0; j < 4; ++j, ++idx) {
        int m = (512 * (p + 2*j)) & (LEN - 1);
        float s, c; sincospif(-(float)m / 4096.0f, &s, &c);
        f[idx]  = make_ulonglong2(pk2(c, c), pk2(-s, s));
        iv[idx] = make_ulonglong2(pk2(c, c), pk2(s, -s));
    }
    #pragma unroll
    for (int j = 0; j < 2; ++j, ++idx) {
        int m = (1024 * (p + 2*j)) & (LEN - 1);
        float s, c; sincospif(-(float)m / 4096.0f, &s, &c);
        f[idx]  = make_ulonglong2(pk2(c, c), pk2(-s, s));
        iv[idx] = make_ulonglong2(pk2(c, c), pk2(s, -s));
    }
    {
        int m = (2048 * p) & (LEN - 1);
        float s, c; sincospif(-(float)m / 4096.0f, &s, &c);
        f[idx]  = make_ulonglong2(pk2(c, c), pk2(-s, s));
        iv[idx] = make_ulonglong2(pk2(c, c), pk2(s, -s));
    }
}

// khat: K_hat[h] = (FFT(K[h]) + D[h]) / L, coalesced [k*512+t]; also writes conv tables.
__global__ void __launch_bounds__(NT, 2) khat_kernel(const float* __restrict__ K,
                                                     const float* __restrict__ D) {
    extern __shared__ u64 sm[];
    const int h = blockIdx.x;
    const int t = threadIdx.x;

    const int g = blockIdx.x * NT + t;
    if (g < 4096) {
        float s, c; sincospif(-(float)g / 4096.0f, &s, &c);
        g_T1f[g] = make_ulonglong2(pk2(c, c), pk2(-s, s));
        g_T1i[g] = make_ulonglong2(pk2(c, c), pk2(s, -s));
        if (g < 256) {
            float s2, c2; sincospif(-(float)(16*g) / 4096.0f, &s2, &c2);
            g_T2f[g] = make_ulonglong2(pk2(c2, c2), pk2(-s2, s2));
            g_T2i[g] = make_ulonglong2(pk2(c2, c2), pk2(s2, -s2));
        }
        if (g < 2) write_c3_row(g, g_C3f + g*15, g_C3i + g*15);
    }

    const float* krow = K + (size_t)h * LEN;
    u64 r[16];
    #pragma unroll
    for (int k = 0; k < 16; ++k) r[k] = pk2(krow[t + 512*k], 0.0f);
    fft_fwd_gen(r, sm, t);
    const float dv = D[h];
    const float invL = 1.0f / (float)LEN;
    float2* out = g_khat + (size_t)h * LEN;
    #pragma unroll
    for (int k = 0; k < 16; ++k) {
        float2 v = upk(r[k]);
        out[k * 512 + t] = make_float2((v.x + dv) * invL, v.y * invL);
    }
}

__global__ void __launch_bounds__(NT, 2) conv_kernel(const float* __restrict__ u,
                                                     float* __restrict__ y) {
    extern __shared__ u64 sm[];
    const int bid = blockIdx.x;           // [0, (BN/2)*HN)
    const int h   = bid >> 2;             // adjacent blocks share khat row -> L2 reuse
    const int bp  = bid & 3;              // batch-pair index
    const int t   = threadIdx.x;

    const size_t row0 = ((size_t)(2*bp) * HN + h) * LEN;
    const size_t row1 = row0 + (size_t)HN * LEN;
    const float* u0 = u + row0;
    const float* u1 = u + row1;

    u64 r[16];
    #pragma unroll
    for (int k = 0; k < 16; ++k)
        r[k] = pk2(__ldcs(u0 + t + 512*k), __ldcs(u1 + t + 512*k));

    fft_fwd(r, sm, t);

    {   // pointwise product with (K_hat + D)/L, coalesced loads
        const float2* kh = g_khat + (size_t)h * LEN;
        #pragma unroll
        for (int k = 0; k < 16; ++k) {
            float2 w = kh[k * 512 + t];
            u64 wxx = pk2(w.x, w.x);
            u64 wyn = pk2(-w.y, w.y);
            r[k] = f2fma(swp(r[k]), wyn, f2mul(r[k], wxx));
        }
    }

    fft_inv(r, sm, t);

    float* y0 = y + row0;
    float* y1 = y + row1;
    #pragma unroll
    for (int k = 0; k < 16; ++k) {
        const int idx = t + 512*k;
        float2 v = upk(r[k]);
        __stcs(y0 + idx, tanh_hw(v.x));
        __stcs(y1 + idx, tanh_hw(v.y));
    }
}

extern "C" void kernel_launch(void* const* d_in, const int* in_sizes, int n_in,
                              void* d_out, int out_size) {
    const float* u = (const float*)d_in[0];   // (B,H,L)
    const float* K = (const float*)d_in[1];   // (H,L)
    const float* D = (const float*)d_in[2];   // (H,)
    float* y = (float*)d_out;                 // (B,H,L)

    const int smem = PD(LEN) * sizeof(u64);   // 67584 B
    cudaFuncSetAttribute(khat_kernel, cudaFuncAttributeMaxDynamicSharedMemorySize, smem);
    cudaFuncSetAttribute(conv_kernel, cudaFuncAttributeMaxDynamicSharedMemorySize, smem);

    khat_kernel<<<HN, NT, smem>>>(K, D);
    conv_kernel<<<(BN/2) * HN, NT, smem>>>(u, y);
}